// round 11
// baseline (speedup 1.0000x reference)
#include <cuda_runtime.h>
#include <cstdint>
#include <cfloat>

// Problem constants (fixed by the dataset)
constexpr int Bv  = 16;      // batch
constexpr int Nv  = 16384;   // pixels
constexpr int Dv  = 64;      // embed dim
constexpr int Kv  = 64;      // templates
constexpr int D4v = 16;      // float4 chunks per vector
constexpr int WPB = 4;       // warps per block = pixels per block
constexpr float EPS_T = 0.5f;  // tf32 screening margin (biased dists)
constexpr float EPS_F = 1e-3f; // fp32 near-tie margin -> fp64 tier
constexpr int CAP = 8;         // per-thread candidate cache

using ull = unsigned long long;

// m16n8k8 tf32 mma.sync (HMMA fallback path on sm_103a; throughput is ample here)
__device__ __forceinline__ void mma_tf32(float* d, const unsigned* a,
                                         const unsigned* b, const float* c) {
    asm volatile(
        "mma.sync.aligned.m16n8k8.row.col.f32.tf32.tf32.f32 "
        "{%0,%1,%2,%3}, {%4,%5,%6,%7}, {%8,%9}, {%10,%11,%12,%13};"
        : "=f"(d[0]), "=f"(d[1]), "=f"(d[2]), "=f"(d[3])
        : "r"(a[0]), "r"(a[1]), "r"(a[2]), "r"(a[3]),
          "r"(b[0]), "r"(b[1]),
          "f"(c[0]), "f"(c[1]), "f"(c[2]), "f"(c[3]));
}

struct Pix {                       // per-pixel smem (22400 B, 16B-multiple)
    float4 ts[Kv * 17];            // t tile, pitch 17 float4 (68 floats)
    float4 xs[Bv * 17];            // x tile
    float  t2s[Kv];
    float  x2s[Bv];
    ull    ref32[Bv];
    ull    ref64[Bv];
    int    cnt[Bv];
};
constexpr int SMEM_BYTES = WPB * (int)sizeof(Pix) + 4 * Bv * WPB * (int)sizeof(float);

__global__ __launch_bounds__(32 * WPB, 2)
void osc_kernel(const float4* __restrict__ xg,     // frame_embeddings [B,N,D] f32
                const float4* __restrict__ tg,     // templates        [K,N,D] f32
                const int*    __restrict__ tcls,   // template_classes [K] int32
                float* __restrict__ out)
{
    extern __shared__ char smem_raw[];
    Pix*   pix  = reinterpret_cast<Pix*>(smem_raw);
    float* obuf = reinterpret_cast<float*>(smem_raw + WPB * sizeof(Pix)); // [4][16][WPB]

    const int tid  = threadIdx.x;
    const int w    = tid >> 5;          // warp = pixel slot
    const int lane = tid & 31;
    const int n0   = blockIdx.x * WPB;
    const int n    = n0 + w;
    Pix& P = pix[w];

    // ---- stage tiles (coalesced; pitch 17 float4) ----
#pragma unroll
    for (int i = 0; i < 32; ++i) {
        int idx = lane + i * 32, k = idx >> 4, d4 = idx & 15;
        P.ts[k * 17 + d4] = tg[((size_t)k * Nv + n) * D4v + d4];
    }
#pragma unroll
    for (int i = 0; i < 8; ++i) {
        int idx = lane + i * 32, b = idx >> 4, d4 = idx & 15;
        P.xs[b * 17 + d4] = xg[((size_t)b * Nv + n) * D4v + d4];
    }
    if (lane < Bv) {
        P.cnt[lane]   = 0;
        P.ref32[lane] = ~0ULL;
        P.ref64[lane] = ~0ULL;
    }
    __syncwarp();

    // ---- precise fp32 norms ----
#pragma unroll
    for (int rr = 0; rr < 2; ++rr) {
        const int k = lane + 32 * rr;
        float s0 = 0.f, s1 = 0.f, s2 = 0.f, s3 = 0.f;
#pragma unroll
        for (int d4 = 0; d4 < D4v; ++d4) {
            float4 v = P.ts[k * 17 + d4];
            s0 = fmaf(v.x, v.x, s0); s1 = fmaf(v.y, v.y, s1);
            s2 = fmaf(v.z, v.z, s2); s3 = fmaf(v.w, v.w, s3);
        }
        P.t2s[k] = (s0 + s1) + (s2 + s3);
    }
    if (lane < Bv) {
        float s0 = 0.f, s1 = 0.f, s2 = 0.f, s3 = 0.f;
#pragma unroll
        for (int d4 = 0; d4 < D4v; ++d4) {
            float4 v = P.xs[lane * 17 + d4];
            s0 = fmaf(v.x, v.x, s0); s1 = fmaf(v.y, v.y, s1);
            s2 = fmaf(v.z, v.z, s2); s3 = fmaf(v.w, v.w, s3);
        }
        P.x2s[lane] = (s0 + s1) + (s2 + s3);
    }
    __syncwarp();

    // ---- Phase A: TF32 mma screen. D[16b, 64k] = x . t^T ----
    // Fragment owner (m16n8k8): g = lane>>2, m = lane&3.
    //   acc[j][0] = dot(x[g],   t[8j+2m]);   acc[j][1] = dot(x[g],   t[8j+2m+1])
    //   acc[j][2] = dot(x[g+8], t[8j+2m]);   acc[j][3] = dot(x[g+8], t[8j+2m+1])
    const int g = lane >> 2;
    const int m = lane & 3;
    const float* tsf = reinterpret_cast<const float*>(P.ts);  // pitch 68 floats
    const float* xsf = reinterpret_cast<const float*>(P.xs);

    float acc[8][4];
#pragma unroll
    for (int j = 0; j < 8; ++j)
#pragma unroll
        for (int e = 0; e < 4; ++e) acc[j][e] = 0.f;

#pragma unroll
    for (int kc = 0; kc < 8; ++kc) {
        const int db = kc * 8;                 // d base of this K-chunk
        unsigned a[4];                          // A frag (x, row-major m16k8)
        a[0] = __float_as_uint(xsf[(g)     * 68 + db + m]);
        a[1] = __float_as_uint(xsf[(g + 8) * 68 + db + m]);
        a[2] = __float_as_uint(xsf[(g)     * 68 + db + m + 4]);
        a[3] = __float_as_uint(xsf[(g + 8) * 68 + db + m + 4]);
#pragma unroll
        for (int j = 0; j < 8; ++j) {           // B frag (t, col-major k8n8)
            unsigned bb[2];
            bb[0] = __float_as_uint(tsf[(8 * j + g) * 68 + db + m]);
            bb[1] = __float_as_uint(tsf[(8 * j + g) * 68 + db + m + 4]);
            mma_tf32(acc[j], a, bb, acc[j]);
        }
    }

    // ---- biased dists bd = t2[k] - 2*dot (x2 constant per b; argmin-safe) ----
#pragma unroll
    for (int j = 0; j < 8; ++j) {
        const int k0 = 8 * j + 2 * m;
        const float t20 = P.t2s[k0], t21 = P.t2s[k0 + 1];
        acc[j][0] = t20 - 2.f * acc[j][0];
        acc[j][1] = t21 - 2.f * acc[j][1];
        acc[j][2] = t20 - 2.f * acc[j][2];
        acc[j][3] = t21 - 2.f * acc[j][3];
    }

    // min per b-row, then across the 4 lanes of the group
    float bmA = FLT_MAX, bmB = FLT_MAX;
#pragma unroll
    for (int j = 0; j < 8; ++j) {
        bmA = fminf(bmA, fminf(acc[j][0], acc[j][1]));
        bmB = fminf(bmB, fminf(acc[j][2], acc[j][3]));
    }
#pragma unroll
    for (int mm = 1; mm <= 2; mm <<= 1) {
        bmA = fminf(bmA, __shfl_xor_sync(0xFFFFFFFFu, bmA, mm));
        bmB = fminf(bmB, __shfl_xor_sync(0xFFFFFFFFu, bmB, mm));
    }
    const float limA = bmA + EPS_T;
    const float limB = bmB + EPS_T;

    // ---- pass 1: exact fp32 expansion for screened candidates ----
    float cd[CAP]; int ck_[CAP]; int cb_[CAP]; int nc = 0;
#pragma unroll 1
    for (int j = 0; j < 8; ++j) {
#pragma unroll 1
        for (int e = 0; e < 4; ++e) {
            const float bd  = acc[j][e];
            const float lim = (e >= 2) ? limB : limA;
            if (bd > lim) continue;
            const int b = (e >= 2) ? g + 8 : g;
            const int k = 8 * j + 2 * m + (e & 1);
            float s0 = 0.f, s1 = 0.f, s2 = 0.f, s3 = 0.f;
#pragma unroll
            for (int d4 = 0; d4 < D4v; ++d4) {
                const float4 xv = P.xs[b * 17 + d4];
                const float4 tv = P.ts[k * 17 + d4];
                s0 = fmaf(xv.x, tv.x, s0); s1 = fmaf(xv.y, tv.y, s1);
                s2 = fmaf(xv.z, tv.z, s2); s3 = fmaf(xv.w, tv.w, s3);
            }
            const float dot = (s0 + s1) + (s2 + s3);
            const float d = P.x2s[b] + P.t2s[k] - 2.f * dot;  // ref-matching expansion
            const ull key = ((ull)__float_as_uint(d) << 6) | (ull)k;
            atomicMin(&P.ref32[b], key);
            if (nc < CAP) { cd[nc] = d; ck_[nc] = k; cb_[nc] = b; ++nc; }
            else atomicAdd(&P.cnt[b], 1);      // overflow: conservatively contested
        }
    }
    __syncwarp();

    // ---- pass 2: detect fp32 near-ties (second candidate within EPS_F) ----
#pragma unroll
    for (int q = 0; q < CAP; ++q) {
        if (q < nc) {
            const ull best = P.ref32[cb_[q]];
            const ull mykey = ((ull)__float_as_uint(cd[q]) << 6) | (ull)ck_[q];
            const float bval = __uint_as_float((unsigned)(best >> 6));
            if (mykey != best && cd[q] <= bval + EPS_F) atomicAdd(&P.cnt[cb_[q]], 1);
        }
    }
    __syncwarp();

    // ---- pass 3 (RARE): fp64 exact adjudication for contested b ----
#pragma unroll 1
    for (int j = 0; j < 8; ++j) {
#pragma unroll 1
        for (int e = 0; e < 4; ++e) {
            const float bd  = acc[j][e];
            const float lim = (e >= 2) ? limB : limA;
            if (bd > lim) continue;
            const int b = (e >= 2) ? g + 8 : g;
            if (P.cnt[b] == 0) continue;
            const int k = 8 * j + 2 * m + (e & 1);
            double dd = 0.0;
#pragma unroll 1
            for (int d4 = 0; d4 < D4v; ++d4) {
                const float4 xv = P.xs[b * 17 + d4];
                const float4 tv = P.ts[k * 17 + d4];
                const double e0 = (double)xv.x - (double)tv.x;
                const double e1 = (double)xv.y - (double)tv.y;
                const double e2 = (double)xv.z - (double)tv.z;
                const double e3 = (double)xv.w - (double)tv.w;
                dd = fma(e0, e0, dd); dd = fma(e1, e1, dd);
                dd = fma(e2, e2, dd); dd = fma(e3, e3, dd);
            }
            const ull key = ((ull)__float_as_uint((float)dd) << 6) | (ull)k;
            atomicMin(&P.ref64[b], key);
        }
    }
    __syncwarp();

    // ---- finalize per b into obuf ----
    if (lane < Bv) {
        const ull key = (P.cnt[lane] > 0) ? P.ref64[lane] : P.ref32[lane];
        const int   bk = (int)(key & 63ULL);
        const float bv = __uint_as_float((unsigned)(key >> 6));
        obuf[(0 * Bv + lane) * WPB + w] = (bv <= 0.5f) ? 1.0f : 0.0f;
        obuf[(1 * Bv + lane) * WPB + w] = (bv <= 1.0f) ? 1.0f : 0.0f;
        obuf[(2 * Bv + lane) * WPB + w] = bv;
        obuf[(3 * Bv + lane) * WPB + w] = (float)__ldg(&tcls[bk]);
    }
    __syncthreads();

    // ---- block epilogue: float4 stores (4 consecutive pixels wide) ----
    if (tid < 4 * Bv) {
        const int o = tid >> 4;
        const int b = tid & 15;
        const size_t BN = (size_t)Bv * Nv;
        const float4 v = *reinterpret_cast<const float4*>(&obuf[(o * Bv + b) * WPB]);
        *reinterpret_cast<float4*>(&out[(size_t)o * BN + (size_t)b * Nv + n0]) = v;
    }
}

extern "C" void kernel_launch(void* const* d_in, const int* in_sizes, int n_in,
                              void* d_out, int out_size)
{
    const float4* frame = (const float4*)d_in[0];   // [16,16384,64] f32
    const float4* tmpl  = (const float4*)d_in[1];   // [64,16384,64] f32
    const int*    tcls  = (const int*)d_in[2];      // [64] int32
    float*        out   = (float*)d_out;

    cudaFuncSetAttribute(osc_kernel,
                         cudaFuncAttributeMaxDynamicSharedMemorySize, SMEM_BYTES);
    osc_kernel<<<Nv / WPB, 32 * WPB, SMEM_BYTES>>>(frame, tmpl, tcls, out);
}

// round 12
// speedup vs baseline: 1.8181x; 1.8181x over previous
#include <cuda_runtime.h>
#include <cstdint>
#include <cfloat>

// Problem constants (fixed by the dataset)
constexpr int Bv  = 16;      // batch
constexpr int Nv  = 16384;   // pixels
constexpr int Dv  = 64;      // embed dim
constexpr int Kv  = 64;      // templates
constexpr int D4v = 16;      // float4 chunks per vector
constexpr int D4H = 8;       // float4 chunks per d-half
constexpr int PPB = 2;       // pixels per block (warp-pair each -> all 4 SMSPs)
constexpr float EPS = 1e-3f; // near-tie margin (>> fp32 dist error ~1e-5)

using ull = unsigned long long;

// ---- packed f32x2 helpers (per-lane rounding identical to fmaf) ----
__device__ __forceinline__ ull f2_fma(ull a, ull b, ull c) {
    ull d;
    asm("fma.rn.f32x2 %0, %1, %2, %3;" : "=l"(d) : "l"(a), "l"(b), "l"(c));
    return d;
}
__device__ __forceinline__ void f2_unpack(ull p, float& lo, float& hi) {
    unsigned a, b;
    asm("mov.b64 {%0, %1}, %2;" : "=r"(a), "=r"(b) : "l"(p));
    lo = __uint_as_float(a); hi = __uint_as_float(b);
}

// XOR swizzles within an 8-chunk half (conflict-free for staging, x-norm,
// and main-loop octets; verified per 8-lane phase)
__device__ __forceinline__ int tswh(int k, int d) { return k * 8 + (d ^ (k & 7)); }
__device__ __forceinline__ int xswh(int b, int d) { return b * 8 + (d ^ (b & 7)); }

__global__ __launch_bounds__(128, 5)
void osc_kernel(const float4* __restrict__ xg,     // frame_embeddings [B,N,D] f32
                const float4* __restrict__ tg,     // templates        [K,N,D] f32
                const int*    __restrict__ tcls,   // template_classes [K] int32
                float* __restrict__ out)
{
    __shared__ __align__(16) float4 ts[PPB][Kv * 8];   // t half-tiles (8KB/pixel)
    __shared__ __align__(16) float4 xs[PPB][Bv * 8];   // x half-tiles (2KB/pixel)
    __shared__ float t2s[PPB][Kv];
    __shared__ float x2s[PPB][Bv];
    __shared__ float clsf[Kv];
    __shared__ float rv[PPB][Bv][17];                  // pitch 17: conflict-free scan
    __shared__ int   ri[PPB][Bv][17];
    __shared__ float bestvs[PPB][Bv];
    __shared__ int   bestks[PPB][Bv];
    __shared__ int   cnt[PPB][Bv];
    __shared__ ull   refined[PPB][Bv];

    const int tid = threadIdx.x;
    const int p   = tid >> 6;            // pixel slot 0/1 (warps 0,1 | 2,3)
    const int q   = tid & 63;            // thread id within pixel
    const int n   = blockIdx.x * PPB + p;

    if (tid < Kv) clsf[tid] = (float)tcls[tid];
    if (q < Bv) {
        cnt[p][q]     = 0;
        refined[p][q] = 0xFFFFFFFFFFFFFFFFULL;
    }

    // thread tile coords: b in {c, c+4, c+8, c+12}, k in {r, r+16, r+32, r+48}
    const int c = q & 3;
    const int r = q >> 2;

    ull acc2[4][4];                      // (even-d, odd-d) partial dots
#pragma unroll
    for (int i = 0; i < 4; ++i)
#pragma unroll
        for (int j = 0; j < 4; ++j) acc2[i][j] = 0ULL;
    ull acct2[4];                        // folded t-norms (valid on c==0 threads)
#pragma unroll
    for (int j = 0; j < 4; ++j) acct2[j] = 0ULL;
    float x2loc = 0.f;                   // x-norm (valid on q<16 threads)

    // ---- two d-halves: stage 8 chunks, accumulate (acc carried in regs) ----
#pragma unroll
    for (int h = 0; h < 2; ++h) {
        __syncthreads();                 // previous half consumed before restage
        // stage t half: 512 float4 per pixel, coalesced (4 x 128B per warp-instr)
#pragma unroll
        for (int i = 0; i < 8; ++i) {
            int idx = q + i * 64;
            int k   = idx >> 3;
            int d   = idx & 7;
            ts[p][tswh(k, d)] = tg[((size_t)k * Nv + n) * D4v + h * D4H + d];
        }
        // stage x half: 128 float4 per pixel
#pragma unroll
        for (int i = 0; i < 2; ++i) {
            int idx = q + i * 64;
            int b   = idx >> 3;
            int d   = idx & 7;
            xs[p][xswh(b, d)] = xg[((size_t)b * Nv + n) * D4v + h * D4H + d];
        }
        __syncthreads();

        // x-norm partial from this half (q<16)
        if (q < Bv) {
            float s0 = 0.f, s1 = 0.f, s2 = 0.f, s3 = 0.f;
#pragma unroll
            for (int d = 0; d < D4H; ++d) {
                float4 v = xs[p][xswh(q, d)];
                s0 = fmaf(v.x, v.x, s0); s1 = fmaf(v.y, v.y, s1);
                s2 = fmaf(v.z, v.z, s2); s3 = fmaf(v.w, v.w, s3);
            }
            x2loc += (s0 + s1) + (s2 + s3);
        }

        // main loop over this half's 8 chunks
#pragma unroll
        for (int d = 0; d < D4H; ++d) {
            ulonglong2 xv[4], tv[4];
#pragma unroll
            for (int i = 0; i < 4; ++i)
                xv[i] = *reinterpret_cast<const ulonglong2*>(&xs[p][xswh(c + 4 * i, d)]);
#pragma unroll
            for (int j = 0; j < 4; ++j)
                tv[j] = *reinterpret_cast<const ulonglong2*>(&ts[p][tswh(r + 16 * j, d)]);
#pragma unroll
            for (int i = 0; i < 4; ++i)
#pragma unroll
                for (int j = 0; j < 4; ++j) {
                    acc2[i][j] = f2_fma(xv[i].x, tv[j].x, acc2[i][j]);
                    acc2[i][j] = f2_fma(xv[i].y, tv[j].y, acc2[i][j]);
                }
            // folded t-norm (result used from c==0 threads only)
#pragma unroll
            for (int j = 0; j < 4; ++j) {
                acct2[j] = f2_fma(tv[j].x, tv[j].x, acct2[j]);
                acct2[j] = f2_fma(tv[j].y, tv[j].y, acct2[j]);
            }
        }
    }

    // publish norms
    if (q < Bv) x2s[p][q] = x2loc;
    if (c == 0) {
#pragma unroll
        for (int j = 0; j < 4; ++j) {
            float lo, hi;
            f2_unpack(acct2[j], lo, hi);
            t2s[p][r + 16 * j] = lo + hi;
        }
    }
    __syncthreads();

    // ---- distances; per-thread min+argmin over its 4 k's per b ----
    float df[4][4];
#pragma unroll
    for (int i = 0; i < 4; ++i) {
        const int   b   = c + 4 * i;
        const float bx2 = x2s[p][b];
        float bestv = FLT_MAX;
        int   bestk = Kv;
#pragma unroll
        for (int j = 0; j < 4; ++j) {
            const int k = r + 16 * j;
            float lo, hi;
            f2_unpack(acc2[i][j], lo, hi);
            const float dot = lo + hi;
            const float d = bx2 + t2s[p][k] - 2.0f * dot;
            df[i][j] = d;
            if (d < bestv) { bestv = d; bestk = k; }  // j asc => first-min
        }
        rv[p][b][r] = bestv;
        ri[p][b][r] = bestk;
    }
    __syncthreads();

    // ---- fp32 min + argmin per b (q<16) ----
    if (q < Bv) {
        float bestv = rv[p][q][0];
        int   bestk = ri[p][q][0];
#pragma unroll
        for (int t = 1; t < 16; ++t) {
            const float v = rv[p][q][t];
            const int   k = ri[p][q][t];
            if (v < bestv || (v == bestv && k < bestk)) { bestv = v; bestk = k; }
        }
        bestvs[p][q] = bestv;
        bestks[p][q] = bestk;
    }
    __syncthreads();

    // ---- near-tie candidate count per b ----
#pragma unroll
    for (int i = 0; i < 4; ++i) {
        const int b = c + 4 * i;
        const float lim = bestvs[p][b] + EPS;
        int local = 0;
#pragma unroll
        for (int j = 0; j < 4; ++j) local += (df[i][j] <= lim) ? 1 : 0;
        if (local) atomicAdd(&cnt[p][b], local);
    }
    __syncthreads();

    // ---- Phase B (RARE): exact fp64 refinement; rows re-read from gmem ----
#pragma unroll
    for (int i = 0; i < 4; ++i) {
        const int b = c + 4 * i;
        if (cnt[p][b] < 2) continue;                  // uncontested: skip fp64
        const float lim = bestvs[p][b] + EPS;
#pragma unroll
        for (int j = 0; j < 4; ++j) {
            if (df[i][j] > lim) continue;
            const int k = r + 16 * j;
            const float4* xrow = &xg[((size_t)b * Nv + n) * D4v];
            const float4* trow = &tg[((size_t)k * Nv + n) * D4v];
            double dd = 0.0;
#pragma unroll 1
            for (int d4 = 0; d4 < D4v; ++d4) {
                const float4 xv = __ldg(xrow + d4);
                const float4 tv = __ldg(trow + d4);
                const double e0 = (double)xv.x - (double)tv.x;
                const double e1 = (double)xv.y - (double)tv.y;
                const double e2 = (double)xv.z - (double)tv.z;
                const double e3 = (double)xv.w - (double)tv.w;
                dd = fma(e0, e0, dd); dd = fma(e1, e1, dd);
                dd = fma(e2, e2, dd); dd = fma(e3, e3, dd);
            }
            const float dfx = (float)dd;              // exact -> fp32
            const ull key = ((ull)__float_as_uint(dfx) << 6) | (ull)k;
            atomicMin(&refined[p][b], key);
        }
    }
    __syncthreads();

    // ---- outputs ----
    if (q < Bv) {
        float bestv;
        int   bestk;
        if (cnt[p][q] >= 2) {
            const ull key = refined[p][q];
            bestk = (int)(key & 63ULL);
            bestv = __uint_as_float((unsigned int)(key >> 6));
        } else {
            bestv = bestvs[p][q];
            bestk = bestks[p][q];
        }
        const size_t BN = (size_t)Bv * Nv;
        const size_t o  = (size_t)q * Nv + n;
        out[o]           = (bestv <= 0.5f) ? 1.0f : 0.0f;  // mask @ 0.5
        out[BN + o]      = (bestv <= 1.0f) ? 1.0f : 0.0f;  // mask @ 1.0
        out[2 * BN + o]  = bestv;                          // min_dists
        out[3 * BN + o]  = clsf[bestk];                    // pred_classes
    }
}

extern "C" void kernel_launch(void* const* d_in, const int* in_sizes, int n_in,
                              void* d_out, int out_size)
{
    const float4* frame = (const float4*)d_in[0];   // [16,16384,64] f32
    const float4* tmpl  = (const float4*)d_in[1];   // [64,16384,64] f32
    const int*    tcls  = (const int*)d_in[2];      // [64] int32
    float*        out   = (float*)d_out;

    osc_kernel<<<Nv / PPB, 64 * PPB>>>(frame, tmpl, tcls, out);
}